// round 1
// baseline (speedup 1.0000x reference)
#include <cuda_runtime.h>
#include <cstdint>

#define IN_DIM  128
#define HID_DIM 128
#define OUT_DIM 64
#define MAX_N   100000

// ---------------- device scratch (no allocations allowed) ----------------
__device__ float g_deg[MAX_N];
__device__ float g_dinv[MAX_N];
__device__ float g_s[MAX_N];
__device__ float g_h0[(size_t)MAX_N * HID_DIM];   // x @ W1
__device__ float g_acc[(size_t)MAX_N * HID_DIM];  // conv1 accumulator
__device__ float g_y[HID_DIM];                    // weighted sum of relu'd h
__device__ int   g_is32;                          // edge_index dtype flag

// ---------------- index dtype detection ----------------
__global__ void detect_idx_kernel(const void* ei, int n) {
    // If data is int32, reading as int64 packs two node ids; high half is a
    // node id (nonzero w.h.p.) -> value >= n. 8 samples => P(miss) ~ 1e-40.
    const long long* p = (const long long*)ei;
    int bad = 0;
    for (int i = 0; i < 8; i++) {
        long long v = p[i];
        if (v < 0 || v >= (long long)n) bad = 1;
    }
    g_is32 = bad;
}

__device__ __forceinline__ int load_idx(const void* ei, size_t i) {
    if (g_is32) return ((const int*)ei)[i];
    return (int)((const long long*)ei)[i];
}

// ---------------- degree / normalization ----------------
__global__ void init_deg_kernel(int n) {
    int i = blockIdx.x * blockDim.x + threadIdx.x;
    if (i < n) g_deg[i] = 1.0f;   // self loop
}

__global__ void count_deg_kernel(const void* ei, int E) {
    int e = blockIdx.x * blockDim.x + threadIdx.x;
    if (e >= E) return;
    int c = load_idx(ei, (size_t)E + e);   // target
    atomicAdd(&g_deg[c], 1.0f);
}

__global__ void dinv_kernel(int n) {
    int i = blockIdx.x * blockDim.x + threadIdx.x;
    if (i < n) {
        float d = rsqrtf(g_deg[i]);
        g_dinv[i] = d;
        g_s[i] = d;   // self-loop term of s[v] = dinv[v] + sum dinv[col]
    }
}

__global__ void accum_s_kernel(const void* ei, int E) {
    int e = blockIdx.x * blockDim.x + threadIdx.x;
    if (e >= E) return;
    int r = load_idx(ei, e);
    int c = load_idx(ei, (size_t)E + e);
    atomicAdd(&g_s[r], g_dinv[c]);
}

// ---------------- GEMM1: h0 = x @ W1  (N x 128) @ (128 x 128) ----------------
// 64 rows per block, 256 threads, each thread: 8 rows x 4 cols.
__global__ __launch_bounds__(256) void gemm1_kernel(
    const float* __restrict__ x, const float* __restrict__ W, int n)
{
    __shared__ float Xs[64][128];   // 32 KB
    __shared__ float Ws[32][128];   // 16 KB
    int t  = threadIdx.x;
    int tx = t & 31;   // column lane
    int ty = t >> 5;   // row group 0..7
    int row0 = blockIdx.x * 64;

    // load X tile (2048 float4)
    const float4* xg = (const float4*)x;
    #pragma unroll
    for (int i = 0; i < 8; i++) {
        int idx = t + i * 256;
        int r = idx >> 5, c4 = idx & 31;
        float4 v;
        if (row0 + r < n) v = xg[(size_t)(row0 + r) * 32 + c4];
        else              v = make_float4(0.f, 0.f, 0.f, 0.f);
        *((float4*)&Xs[r][c4 * 4]) = v;
    }

    float acc[8][4];
    #pragma unroll
    for (int r = 0; r < 8; r++)
        #pragma unroll
        for (int j = 0; j < 4; j++) acc[r][j] = 0.f;

    for (int kc = 0; kc < 4; kc++) {
        __syncthreads();
        const float4* wg = (const float4*)(W + kc * 32 * 128);
        #pragma unroll
        for (int i = 0; i < 4; i++) {
            int idx = t + i * 256;
            int r = idx >> 5, c4 = idx & 31;
            *((float4*)&Ws[r][c4 * 4]) = wg[idx];
        }
        __syncthreads();
        #pragma unroll
        for (int kk = 0; kk < 32; kk++) {
            float w0 = Ws[kk][tx];
            float w1 = Ws[kk][tx + 32];
            float w2 = Ws[kk][tx + 64];
            float w3 = Ws[kk][tx + 96];
            #pragma unroll
            for (int r = 0; r < 8; r++) {
                float xv = Xs[ty * 8 + r][kc * 32 + kk];
                acc[r][0] = fmaf(xv, w0, acc[r][0]);
                acc[r][1] = fmaf(xv, w1, acc[r][1]);
                acc[r][2] = fmaf(xv, w2, acc[r][2]);
                acc[r][3] = fmaf(xv, w3, acc[r][3]);
            }
        }
    }

    #pragma unroll
    for (int r = 0; r < 8; r++) {
        int row = row0 + ty * 8 + r;
        if (row < n) {
            float* o = g_h0 + (size_t)row * 128;
            o[tx]      = acc[r][0];
            o[tx + 32] = acc[r][1];
            o[tx + 64] = acc[r][2];
            o[tx + 96] = acc[r][3];
        }
    }
}

// ---------------- init acc with self-loop term: acc[i] = dinv[i]^2 * h0[i] ----
__global__ void init_acc_kernel(int n) {
    int idx = blockIdx.x * blockDim.x + threadIdx.x;  // over n*32 float4
    if (idx >= n * 32) return;
    int row = idx >> 5;
    float d = g_dinv[row];
    float nn = d * d;
    float4 v = ((const float4*)g_h0)[idx];
    v.x *= nn; v.y *= nn; v.z *= nn; v.w *= nn;
    ((float4*)g_acc)[idx] = v;
}

// ---------------- layer-1 scatter: warp per edge, vector RED ----------------
__global__ __launch_bounds__(256) void scatter1_kernel(const void* ei, int E) {
    int warp = (blockIdx.x * blockDim.x + threadIdx.x) >> 5;
    int lane = threadIdx.x & 31;
    if (warp >= E) return;
    int r = load_idx(ei, warp);
    int c = load_idx(ei, (size_t)E + warp);
    float norm = g_dinv[r] * g_dinv[c];
    float4 v = ((const float4*)(g_h0 + (size_t)r * 128))[lane];
    v.x *= norm; v.y *= norm; v.z *= norm; v.w *= norm;
    float* dst = g_acc + (size_t)c * 128 + lane * 4;
    asm volatile("red.global.add.v4.f32 [%0], {%1, %2, %3, %4};"
                 :: "l"(dst), "f"(v.x), "f"(v.y), "f"(v.z), "f"(v.w)
                 : "memory");
}

// ---------------- zero y ----------------
__global__ void zero_y_kernel() {
    g_y[threadIdx.x] = 0.f;
}

// ---------------- fused relu + weighted reduce: y = sum_v c[v]*relu(acc[v]+b1) --
__global__ __launch_bounds__(128) void reduce_y_kernel(
    const float* __restrict__ b1, int n)
{
    int f = threadIdx.x;   // 128
    float b = b1[f];
    float local = 0.f;
    for (int i = blockIdx.x; i < n; i += gridDim.x) {
        float cv = g_dinv[i] * g_s[i];
        float hv = g_acc[(size_t)i * 128 + f] + b;
        hv = fmaxf(hv, 0.f);
        local = fmaf(cv, hv, local);
    }
    atomicAdd(&g_y[f], local);
}

// ---------------- final: out = (y @ W2)/N + b2 ----------------
__global__ void final_kernel(const float* __restrict__ W2,
                             const float* __restrict__ b2,
                             float* __restrict__ out, int n)
{
    int f = threadIdx.x;   // 64
    float sum = 0.f;
    #pragma unroll 8
    for (int k = 0; k < 128; k++)
        sum = fmaf(g_y[k], W2[k * 64 + f], sum);
    out[f] = sum / (float)n + b2[f];
}

// ---------------- launch ----------------
extern "C" void kernel_launch(void* const* d_in, const int* in_sizes, int n_in,
                              void* d_out, int out_size)
{
    const float* x  = (const float*)d_in[0];
    const void*  ei = d_in[1];
    const float* W1 = (const float*)d_in[2];
    const float* b1 = (const float*)d_in[3];
    const float* W2 = (const float*)d_in[4];
    const float* b2 = (const float*)d_in[5];
    float* out = (float*)d_out;

    int n = in_sizes[0] / IN_DIM;     // 100000
    int E = in_sizes[1] / 2;          // 1600000

    detect_idx_kernel<<<1, 1>>>(ei, n);
    init_deg_kernel<<<(n + 255) / 256, 256>>>(n);
    count_deg_kernel<<<(E + 255) / 256, 256>>>(ei, E);
    dinv_kernel<<<(n + 255) / 256, 256>>>(n);
    accum_s_kernel<<<(E + 255) / 256, 256>>>(ei, E);

    gemm1_kernel<<<(n + 63) / 64, 256>>>(x, W1, n);
    init_acc_kernel<<<(n * 32 + 255) / 256, 256>>>(n);
    scatter1_kernel<<<(E * 32 + 255) / 256, 256>>>(ei, E);

    zero_y_kernel<<<1, 128>>>();
    reduce_y_kernel<<<2048, 128>>>(b1, n);
    final_kernel<<<1, 64>>>(W2, b2, out, n);
}

// round 2
// speedup vs baseline: 1.8519x; 1.8519x over previous
#include <cuda_runtime.h>
#include <cstdint>

#define IN_DIM  128
#define HID_DIM 128
#define OUT_DIM 64
#define MAX_N   100000
#define MAX_E   1700000

// ---------------- device scratch (no allocations allowed) ----------------
__device__ float g_deg[MAX_N];
__device__ float g_dinv[MAX_N];
__device__ float g_s[MAX_N];
__device__ int   g_off[MAX_N];      // bin start offsets (exclusive scan of cnt)
__device__ int   g_cursor[MAX_N];   // fill cursors
__device__ int   g_bsum[512];       // per-block scan partials
__device__ int   g_bscan[512];      // exclusive scan of partials
__device__ int   g_bin[MAX_E];      // src node per edge, binned by dst
__device__ float g_h0[(size_t)MAX_N * HID_DIM];   // x @ W1
__device__ float g_y[HID_DIM];      // weighted sum of relu'd hidden
__device__ int   g_is32;            // edge_index dtype flag

// ---------------- index dtype detection ----------------
__global__ void detect_idx_kernel(const void* ei, int n) {
    const long long* p = (const long long*)ei;
    int bad = 0;
    for (int i = 0; i < 8; i++) {
        long long v = p[i];
        if (v < 0 || v >= (long long)n) bad = 1;
    }
    g_is32 = bad;
}

__device__ __forceinline__ int load_idx(const void* ei, size_t i) {
    if (g_is32) return ((const int*)ei)[i];
    return (int)((const long long*)ei)[i];
}

// ---------------- degree / normalization ----------------
__global__ void init_deg_kernel(int n) {
    int i = blockIdx.x * blockDim.x + threadIdx.x;
    if (i < n) g_deg[i] = 1.0f;   // self loop
}

__global__ void count_deg_kernel(const void* ei, int E) {
    int e = blockIdx.x * blockDim.x + threadIdx.x;
    if (e >= E) return;
    int c = load_idx(ei, (size_t)E + e);   // target
    atomicAdd(&g_deg[c], 1.0f);
}

__global__ void dinv_kernel(int n) {
    int i = blockIdx.x * blockDim.x + threadIdx.x;
    if (i < n) {
        float d = rsqrtf(g_deg[i]);
        g_dinv[i] = d;
        g_s[i] = d;   // self-loop term of s[v]
    }
}

// ---------------- prefix scan of per-node edge counts ----------------
__global__ void scan1_kernel(int n) {
    __shared__ int sh[256];
    int t = threadIdx.x;
    int i = blockIdx.x * 256 + t;
    int v = (i < n) ? ((int)g_deg[i] - 1) : 0;
    sh[t] = v;
    __syncthreads();
    #pragma unroll
    for (int ofs = 1; ofs < 256; ofs <<= 1) {
        int a = (t >= ofs) ? sh[t - ofs] : 0;
        __syncthreads();
        sh[t] += a;
        __syncthreads();
    }
    if (i < n) g_off[i] = sh[t] - v;       // exclusive
    if (t == 255) g_bsum[blockIdx.x] = sh[255];
}

__global__ void scan2_kernel(int nb) {
    __shared__ int sh[512];
    int t = threadIdx.x;
    int v = (t < nb) ? g_bsum[t] : 0;
    sh[t] = v;
    __syncthreads();
    #pragma unroll
    for (int ofs = 1; ofs < 512; ofs <<= 1) {
        int a = (t >= ofs) ? sh[t - ofs] : 0;
        __syncthreads();
        sh[t] += a;
        __syncthreads();
    }
    g_bscan[t] = sh[t] - v;                // exclusive
}

__global__ void scan3_kernel(int n) {
    int i = blockIdx.x * blockDim.x + threadIdx.x;
    if (i >= n) return;
    int o = g_off[i] + g_bscan[i >> 8];
    g_off[i] = o;
    g_cursor[i] = o;
}

// ---------------- bin fill (fused with s accumulation) ----------------
__global__ void binfill_kernel(const void* ei, int E) {
    int e = blockIdx.x * blockDim.x + threadIdx.x;
    if (e >= E) return;
    int r = load_idx(ei, e);
    int c = load_idx(ei, (size_t)E + e);
    atomicAdd(&g_s[r], g_dinv[c]);
    int pos = atomicAdd(&g_cursor[c], 1);
    g_bin[pos] = r;
}

// ---------------- GEMM1: h0 = x @ W1 ----------------
__global__ __launch_bounds__(256) void gemm1_kernel(
    const float* __restrict__ x, const float* __restrict__ W, int n)
{
    __shared__ float Xs[64][128];   // 32 KB
    __shared__ float Ws[32][128];   // 16 KB
    int t  = threadIdx.x;
    int tx = t & 31;   // col group: cols [4tx, 4tx+4)
    int ty = t >> 5;   // row group 0..7
    int row0 = blockIdx.x * 64;

    const float4* xg = (const float4*)x;
    #pragma unroll
    for (int i = 0; i < 8; i++) {
        int idx = t + i * 256;
        int r = idx >> 5, c4 = idx & 31;
        float4 v;
        if (row0 + r < n) v = xg[(size_t)(row0 + r) * 32 + c4];
        else              v = make_float4(0.f, 0.f, 0.f, 0.f);
        *((float4*)&Xs[r][c4 * 4]) = v;
    }

    float4 acc[8];
    #pragma unroll
    for (int r = 0; r < 8; r++) acc[r] = make_float4(0.f, 0.f, 0.f, 0.f);

    for (int kc = 0; kc < 4; kc++) {
        __syncthreads();
        const float4* wg = (const float4*)(W + kc * 32 * 128);
        #pragma unroll
        for (int i = 0; i < 4; i++) {
            int idx = t + i * 256;
            int r = idx >> 5, c4 = idx & 31;
            *((float4*)&Ws[r][c4 * 4]) = wg[idx];
        }
        __syncthreads();
        #pragma unroll
        for (int kk = 0; kk < 32; kk++) {
            float4 w = *((const float4*)&Ws[kk][tx * 4]);
            #pragma unroll
            for (int r = 0; r < 8; r++) {
                float xv = Xs[ty * 8 + r][kc * 32 + kk];
                acc[r].x = fmaf(xv, w.x, acc[r].x);
                acc[r].y = fmaf(xv, w.y, acc[r].y);
                acc[r].z = fmaf(xv, w.z, acc[r].z);
                acc[r].w = fmaf(xv, w.w, acc[r].w);
            }
        }
    }

    #pragma unroll
    for (int r = 0; r < 8; r++) {
        int row = row0 + ty * 8 + r;
        if (row < n)
            ((float4*)(g_h0 + (size_t)row * 128))[tx] = acc[r];
    }
}

// ---------------- zero y ----------------
__global__ void zero_y_kernel() {
    g_y[threadIdx.x] = 0.f;
}

// ---------------- fused conv1 + relu + weighted reduce ----------------
// warp per dst node; conv accumulated in registers; y folded per warp.
__global__ __launch_bounds__(256) void fused_conv_kernel(
    const float* __restrict__ b1, int n)
{
    __shared__ float ysh[8 * 128];
    int t = threadIdx.x, lane = t & 31, w = t >> 5;
    float4 bb = ((const float4*)b1)[lane];
    float4 yacc = make_float4(0.f, 0.f, 0.f, 0.f);

    int gw = blockIdx.x * 8 + w;
    int nw = gridDim.x * 8;
    for (int v = gw; v < n; v += nw) {
        float dv = g_dinv[v];
        float4 a = ((const float4*)(g_h0 + (size_t)v * 128))[lane];
        float nn = dv * dv;
        a.x *= nn; a.y *= nn; a.z *= nn; a.w *= nn;

        int off = g_off[v];
        int cnt = (int)g_deg[v] - 1;
        for (int k = 0; k < cnt; k++) {
            int src = g_bin[off + k];
            float nrm = dv * g_dinv[src];
            float4 u = ((const float4*)(g_h0 + (size_t)src * 128))[lane];
            a.x = fmaf(nrm, u.x, a.x);
            a.y = fmaf(nrm, u.y, a.y);
            a.z = fmaf(nrm, u.z, a.z);
            a.w = fmaf(nrm, u.w, a.w);
        }

        float cv = dv * g_s[v];
        yacc.x = fmaf(cv, fmaxf(a.x + bb.x, 0.f), yacc.x);
        yacc.y = fmaf(cv, fmaxf(a.y + bb.y, 0.f), yacc.y);
        yacc.z = fmaf(cv, fmaxf(a.z + bb.z, 0.f), yacc.z);
        yacc.w = fmaf(cv, fmaxf(a.w + bb.w, 0.f), yacc.w);
    }

    *((float4*)&ysh[w * 128 + lane * 4]) = yacc;
    __syncthreads();
    if (t < 128) {
        float s = 0.f;
        #pragma unroll
        for (int i = 0; i < 8; i++) s += ysh[i * 128 + t];
        atomicAdd(&g_y[t], s);
    }
}

// ---------------- final: out = (y @ W2)/N + b2 ----------------
__global__ void final_kernel(const float* __restrict__ W2,
                             const float* __restrict__ b2,
                             float* __restrict__ out, int n)
{
    int f = threadIdx.x;   // 64
    float sum = 0.f;
    #pragma unroll 8
    for (int k = 0; k < 128; k++)
        sum = fmaf(g_y[k], W2[k * 64 + f], sum);
    out[f] = sum / (float)n + b2[f];
}

// ---------------- launch ----------------
extern "C" void kernel_launch(void* const* d_in, const int* in_sizes, int n_in,
                              void* d_out, int out_size)
{
    const float* x  = (const float*)d_in[0];
    const void*  ei = d_in[1];
    const float* W1 = (const float*)d_in[2];
    const float* b1 = (const float*)d_in[3];
    const float* W2 = (const float*)d_in[4];
    const float* b2 = (const float*)d_in[5];
    float* out = (float*)d_out;

    int n = in_sizes[0] / IN_DIM;     // 100000
    int E = in_sizes[1] / 2;          // 1600000
    int nb = (n + 255) / 256;         // scan blocks (<=512)

    detect_idx_kernel<<<1, 1>>>(ei, n);
    init_deg_kernel<<<(n + 255) / 256, 256>>>(n);
    count_deg_kernel<<<(E + 255) / 256, 256>>>(ei, E);
    dinv_kernel<<<(n + 255) / 256, 256>>>(n);

    scan1_kernel<<<nb, 256>>>(n);
    scan2_kernel<<<1, 512>>>(nb);
    scan3_kernel<<<(n + 255) / 256, 256>>>(n);

    binfill_kernel<<<(E + 255) / 256, 256>>>(ei, E);

    gemm1_kernel<<<(n + 63) / 64, 256>>>(x, W1, n);

    zero_y_kernel<<<1, 128>>>();
    fused_conv_kernel<<<1776, 256>>>(b1, n);
    final_kernel<<<1, 64>>>(W2, b2, out, n);
}

// round 3
// speedup vs baseline: 2.0673x; 1.1163x over previous
#include <cuda_runtime.h>
#include <cuda_bf16.h>
#include <cstdint>

#define IN_DIM  128
#define HID_DIM 128
#define OUT_DIM 64
#define MAX_N   100000
#define MAX_E   1700000

// ---------------- device scratch ----------------
__device__ int   g_cnt[MAX_N];      // in-degree (without self loop)
__device__ float g_dinv[MAX_N];
__device__ float g_s[MAX_N];
__device__ int   g_off[MAX_N];
__device__ int   g_cursor[MAX_N];
__device__ int   g_bsum[512];
__device__ int   g_bscan[512];
__device__ int   g_bin[MAX_E];
__device__ __nv_bfloat16 g_h0bf[(size_t)MAX_N * HID_DIM];
__device__ float g_y[HID_DIM];
__device__ int   g_is32;

// ---------------- index dtype detection ----------------
__global__ void detect_idx_kernel(const void* ei, int n) {
    const long long* p = (const long long*)ei;
    int bad = 0;
    for (int i = 0; i < 8; i++) {
        long long v = p[i];
        if (v < 0 || v >= (long long)n) bad = 1;
    }
    g_is32 = bad;
}

__device__ __forceinline__ int load_idx(const void* ei, size_t i) {
    if (g_is32) return ((const int*)ei)[i];
    return (int)((const long long*)ei)[i];
}

// ---------------- degree / normalization ----------------
__global__ void zero_cnt_kernel(int n) {
    int i = blockIdx.x * blockDim.x + threadIdx.x;
    if (i < n) g_cnt[i] = 0;
}

__global__ void count_deg_kernel(const void* ei, int E) {
    int e = blockIdx.x * blockDim.x + threadIdx.x;
    if (e >= E) return;
    int c = load_idx(ei, (size_t)E + e);
    atomicAdd(&g_cnt[c], 1);
}

__global__ void dinv_kernel(int n) {
    int i = blockIdx.x * blockDim.x + threadIdx.x;
    if (i < n) {
        float d = rsqrtf((float)(g_cnt[i] + 1));   // +1 self loop
        g_dinv[i] = d;
        g_s[i] = d;
    }
}

// ---------------- prefix scan ----------------
__global__ void scan1_kernel(int n) {
    __shared__ int sh[256];
    int t = threadIdx.x;
    int i = blockIdx.x * 256 + t;
    int v = (i < n) ? g_cnt[i] : 0;
    sh[t] = v;
    __syncthreads();
    #pragma unroll
    for (int ofs = 1; ofs < 256; ofs <<= 1) {
        int a = (t >= ofs) ? sh[t - ofs] : 0;
        __syncthreads();
        sh[t] += a;
        __syncthreads();
    }
    if (i < n) g_off[i] = sh[t] - v;
    if (t == 255) g_bsum[blockIdx.x] = sh[255];
}

__global__ void scan2_kernel(int nb) {
    __shared__ int sh[512];
    int t = threadIdx.x;
    int v = (t < nb) ? g_bsum[t] : 0;
    sh[t] = v;
    __syncthreads();
    #pragma unroll
    for (int ofs = 1; ofs < 512; ofs <<= 1) {
        int a = (t >= ofs) ? sh[t - ofs] : 0;
        __syncthreads();
        sh[t] += a;
        __syncthreads();
    }
    g_bscan[t] = sh[t] - v;
}

__global__ void scan3_kernel(int n) {
    int i = blockIdx.x * blockDim.x + threadIdx.x;
    if (i >= n) return;
    int o = g_off[i] + g_bscan[i >> 8];
    g_off[i] = o;
    g_cursor[i] = o;
}

// ---------------- bin fill (+ s accumulation) ----------------
__global__ void binfill_kernel(const void* ei, int E) {
    int e = blockIdx.x * blockDim.x + threadIdx.x;
    if (e >= E) return;
    int r = load_idx(ei, e);
    int c = load_idx(ei, (size_t)E + e);
    atomicAdd(&g_s[r], g_dinv[c]);
    int pos = atomicAdd(&g_cursor[c], 1);
    g_bin[pos] = r;
}

// ---------------- GEMM1: h0 = bf16(x @ W1) via mma.sync bf16 ----------------
// block tile 128x128, K=128 resident; 8 warps (4 M x 2 N), warp 32x64.
#define AS_STRIDE 136
__global__ __launch_bounds__(256) void gemm1_kernel(
    const float* __restrict__ x, const float* __restrict__ W, int n)
{
    __shared__ __nv_bfloat16 As[128][AS_STRIDE];
    __shared__ __nv_bfloat16 Ws[128][AS_STRIDE];   // transposed: [n][k]
    int t = threadIdx.x;
    int row0 = blockIdx.x * 128;

    const float4* xg = (const float4*)x;
    #pragma unroll
    for (int i = 0; i < 16; i++) {
        int idx4 = t + i * 256;
        int r = idx4 >> 5, c4 = idx4 & 31;
        float4 v = make_float4(0.f, 0.f, 0.f, 0.f);
        if (row0 + r < n) v = xg[(size_t)(row0 + r) * 32 + c4];
        *(__nv_bfloat162*)&As[r][c4 * 4]     = __floats2bfloat162_rn(v.x, v.y);
        *(__nv_bfloat162*)&As[r][c4 * 4 + 2] = __floats2bfloat162_rn(v.z, v.w);
    }
    const float4* wg = (const float4*)W;
    #pragma unroll
    for (int i = 0; i < 16; i++) {
        int idx4 = t + i * 256;
        int k = idx4 >> 5, n4 = idx4 & 31;
        float4 v = wg[idx4];
        Ws[n4 * 4 + 0][k] = __float2bfloat16(v.x);
        Ws[n4 * 4 + 1][k] = __float2bfloat16(v.y);
        Ws[n4 * 4 + 2][k] = __float2bfloat16(v.z);
        Ws[n4 * 4 + 3][k] = __float2bfloat16(v.w);
    }
    __syncthreads();

    int lane = t & 31, wid = t >> 5;
    int moff = (wid & 3) * 32;
    int noff = (wid >> 2) * 64;
    int g = lane >> 2, tq = lane & 3;

    float acc[2][8][4];
    #pragma unroll
    for (int mt = 0; mt < 2; mt++)
        #pragma unroll
        for (int nt = 0; nt < 8; nt++)
            #pragma unroll
            for (int j = 0; j < 4; j++) acc[mt][nt][j] = 0.f;

    #pragma unroll
    for (int kt = 0; kt < 8; kt++) {
        int k0 = kt * 16;
        uint32_t a[2][4];
        #pragma unroll
        for (int mt = 0; mt < 2; mt++) {
            int r = moff + mt * 16 + g;
            a[mt][0] = *(const uint32_t*)&As[r][k0 + 2 * tq];
            a[mt][1] = *(const uint32_t*)&As[r + 8][k0 + 2 * tq];
            a[mt][2] = *(const uint32_t*)&As[r][k0 + 2 * tq + 8];
            a[mt][3] = *(const uint32_t*)&As[r + 8][k0 + 2 * tq + 8];
        }
        #pragma unroll
        for (int nt = 0; nt < 8; nt++) {
            int c = noff + nt * 8 + g;
            uint32_t b0 = *(const uint32_t*)&Ws[c][k0 + 2 * tq];
            uint32_t b1 = *(const uint32_t*)&Ws[c][k0 + 2 * tq + 8];
            #pragma unroll
            for (int mt = 0; mt < 2; mt++) {
                asm volatile(
                    "mma.sync.aligned.m16n8k16.row.col.f32.bf16.bf16.f32 "
                    "{%0,%1,%2,%3}, {%4,%5,%6,%7}, {%8,%9}, {%0,%1,%2,%3};"
                    : "+f"(acc[mt][nt][0]), "+f"(acc[mt][nt][1]),
                      "+f"(acc[mt][nt][2]), "+f"(acc[mt][nt][3])
                    : "r"(a[mt][0]), "r"(a[mt][1]), "r"(a[mt][2]), "r"(a[mt][3]),
                      "r"(b0), "r"(b1));
            }
        }
    }

    #pragma unroll
    for (int mt = 0; mt < 2; mt++) {
        int r = row0 + moff + mt * 16 + g;
        #pragma unroll
        for (int nt = 0; nt < 8; nt++) {
            int c = noff + nt * 8 + 2 * tq;
            if (r < n)
                *(__nv_bfloat162*)&g_h0bf[(size_t)r * 128 + c] =
                    __floats2bfloat162_rn(acc[mt][nt][0], acc[mt][nt][1]);
            if (r + 8 < n)
                *(__nv_bfloat162*)&g_h0bf[(size_t)(r + 8) * 128 + c] =
                    __floats2bfloat162_rn(acc[mt][nt][2], acc[mt][nt][3]);
        }
    }
}

// ---------------- zero y ----------------
__global__ void zero_y_kernel() {
    g_y[threadIdx.x] = 0.f;
}

// ---------------- fused conv1 + relu + weighted reduce (bf16 gather) --------
__device__ __forceinline__ float4 unpack4(uint2 u) {
    float2 f0 = __bfloat1622float2(*(__nv_bfloat162*)&u.x);
    float2 f1 = __bfloat1622float2(*(__nv_bfloat162*)&u.y);
    return make_float4(f0.x, f0.y, f1.x, f1.y);
}

__global__ __launch_bounds__(256) void fused_conv_kernel(
    const float* __restrict__ b1, int n)
{
    __shared__ float ysh[8 * 128];
    int t = threadIdx.x, lane = t & 31, w = t >> 5;
    float4 bb = ((const float4*)b1)[lane];
    float4 yacc = make_float4(0.f, 0.f, 0.f, 0.f);
    const uint2* h = (const uint2*)g_h0bf;   // 32 x 8B per row

    int gw = blockIdx.x * 8 + w;
    int nw = gridDim.x * 8;
    for (int v = gw; v < n; v += nw) {
        float dv = g_dinv[v];
        float4 sv = unpack4(h[(size_t)v * 32 + lane]);
        float nn = dv * dv;
        float4 a = make_float4(sv.x * nn, sv.y * nn, sv.z * nn, sv.w * nn);

        int off = g_off[v];
        int cnt = g_cnt[v];
        for (int k = 0; k < cnt; k++) {
            int src = g_bin[off + k];
            float nrm = dv * g_dinv[src];
            float4 u = unpack4(h[(size_t)src * 32 + lane]);
            a.x = fmaf(nrm, u.x, a.x);
            a.y = fmaf(nrm, u.y, a.y);
            a.z = fmaf(nrm, u.z, a.z);
            a.w = fmaf(nrm, u.w, a.w);
        }

        float cv = dv * g_s[v];
        yacc.x = fmaf(cv, fmaxf(a.x + bb.x, 0.f), yacc.x);
        yacc.y = fmaf(cv, fmaxf(a.y + bb.y, 0.f), yacc.y);
        yacc.z = fmaf(cv, fmaxf(a.z + bb.z, 0.f), yacc.z);
        yacc.w = fmaf(cv, fmaxf(a.w + bb.w, 0.f), yacc.w);
    }

    *((float4*)&ysh[w * 128 + lane * 4]) = yacc;
    __syncthreads();
    if (t < 128) {
        float s = 0.f;
        #pragma unroll
        for (int i = 0; i < 8; i++) s += ysh[i * 128 + t];
        atomicAdd(&g_y[t], s);
    }
}

// ---------------- final: out = (y @ W2)/N + b2 ----------------
__global__ void final_kernel(const float* __restrict__ W2,
                             const float* __restrict__ b2,
                             float* __restrict__ out, int n)
{
    int f = threadIdx.x;   // 64
    float sum = 0.f;
    #pragma unroll 8
    for (int k = 0; k < 128; k++)
        sum = fmaf(g_y[k], W2[k * 64 + f], sum);
    out[f] = sum / (float)n + b2[f];
}

// ---------------- launch ----------------
extern "C" void kernel_launch(void* const* d_in, const int* in_sizes, int n_in,
                              void* d_out, int out_size)
{
    const float* x  = (const float*)d_in[0];
    const void*  ei = d_in[1];
    const float* W1 = (const float*)d_in[2];
    const float* b1 = (const float*)d_in[3];
    const float* W2 = (const float*)d_in[4];
    const float* b2 = (const float*)d_in[5];
    float* out = (float*)d_out;

    int n = in_sizes[0] / IN_DIM;     // 100000
    int E = in_sizes[1] / 2;          // 1600000
    int nb = (n + 255) / 256;         // scan blocks (<=512)

    detect_idx_kernel<<<1, 1>>>(ei, n);
    zero_cnt_kernel<<<(n + 255) / 256, 256>>>(n);
    count_deg_kernel<<<(E + 255) / 256, 256>>>(ei, E);
    dinv_kernel<<<(n + 255) / 256, 256>>>(n);

    scan1_kernel<<<nb, 256>>>(n);
    scan2_kernel<<<1, 512>>>(nb);
    scan3_kernel<<<(n + 255) / 256, 256>>>(n);

    binfill_kernel<<<(E + 255) / 256, 256>>>(ei, E);

    gemm1_kernel<<<(n + 127) / 128, 256>>>(x, W1, n);

    zero_y_kernel<<<1, 128>>>();
    fused_conv_kernel<<<1776, 256>>>(b1, n);
    final_kernel<<<1, 64>>>(W2, b2, out, n);
}